// round 2
// baseline (speedup 1.0000x reference)
#include <cuda_runtime.h>

#define BB 4
#define KK 200
#define DIMN 256
#define TFRAMES 800
#define TTILE 8

// ---- scratch (no allocations allowed) ----
__device__ float g_start[BB * KK];
__device__ float g_end[BB * KK];
__device__ float g_base1[BB * KK * 16];
__device__ float g_base2[BB * KK * 2];

__device__ __forceinline__ float silu_f(float x) {
    return __fdividef(x, 1.0f + __expf(-x));
}

// ---------------------------------------------------------------------------
// Kernel 1: per-batch cumsum of durations -> token start/end
// ---------------------------------------------------------------------------
__global__ void cumsum_kernel(const float* __restrict__ dur) {
    int b = blockIdx.x;
    if (threadIdx.x == 0) {
        float acc = 0.f;
        for (int k = 0; k < KK; k++) {
            float d = dur[b * KK + k];
            g_start[b * KK + k] = acc;
            acc += d;
            g_end[b * KK + k] = acc;
        }
    }
}

// ---------------------------------------------------------------------------
// Kernel 2: conv1d(same,k=3)+SiLU for both branches, then fold the 8
// t-invariant features through rows 2..9 of sw1_w1 / sw2_w1 into base vectors.
// One block per (b,k).
// ---------------------------------------------------------------------------
__global__ void conv_kernel(const float* __restrict__ features,
                            const float* __restrict__ c1w, const float* __restrict__ c1b,
                            const float* __restrict__ c2w, const float* __restrict__ c2b,
                            const float* __restrict__ sw1w1, const float* __restrict__ sw1b1,
                            const float* __restrict__ sw2w1, const float* __restrict__ sw2b1) {
    int b = blockIdx.x / KK;
    int k = blockIdx.x % KK;
    __shared__ float feat[768];
    __shared__ float leftS[8], rightS[8];
    int tid = threadIdx.x;

#pragma unroll
    for (int j = 0; j < 3; j++) {
        int row = k - 1 + j;
        feat[j * 256 + tid] =
            (row >= 0 && row < KK) ? features[(b * KK + row) * DIMN + tid] : 0.f;
    }
    __syncthreads();

    int w = tid >> 5, lane = tid & 31;
    float sL = 0.f, sR = 0.f;
    for (int i = lane; i < 768; i += 32) {
        int j = i >> 8, d = i & 255;
        float f = feat[i];
        int wi = j * 2048 + d * 8 + w;   // conv_w[j][d][w], [3,256,8]
        sL = fmaf(f, c1w[wi], sL);
        sR = fmaf(f, c2w[wi], sR);
    }
#pragma unroll
    for (int o = 16; o; o >>= 1) {
        sL += __shfl_down_sync(0xffffffffu, sL, o);
        sR += __shfl_down_sync(0xffffffffu, sR, o);
    }
    if (lane == 0) {
        leftS[w]  = silu_f(sL + c1b[w]);
        rightS[w] = silu_f(sR + c2b[w]);
    }
    __syncthreads();

    if (tid < 16) {
        float s = sw1b1[tid];
#pragma unroll
        for (int c = 0; c < 8; c++) s = fmaf(leftS[c], sw1w1[(2 + c) * 16 + tid], s);
        g_base1[(b * KK + k) * 16 + tid] = s;
    } else if (tid < 18) {
        int j = tid - 16;
        float s = sw2b1[j];
#pragma unroll
        for (int c = 0; c < 8; c++) s = fmaf(rightS[c], sw2w1[(2 + c) * 2 + j], s);
        g_base2[(b * KK + k) * 2 + j] = s;
    }
}

// ---------------------------------------------------------------------------
// Kernel 3: fused main kernel. One block = (b, 8 consecutive frames).
// Phase per frame: logits (k-parallel) -> softmax -> C (k-parallel, scaled by
// W so A is a plain smem sum). Then one batched O pass (d-parallel) reusing
// each feature load across all 8 frames.
// ---------------------------------------------------------------------------
__global__ __launch_bounds__(256) void main_kernel(
    const float* __restrict__ features,
    const float* __restrict__ sw1w1, const float* __restrict__ sw1w2,
    const float* __restrict__ sw1b2,
    const float* __restrict__ sw2w1, const float* __restrict__ sw2w2,
    const float* __restrict__ sw2b2,
    const float* __restrict__ p1w, const float* __restrict__ p1b,
    const float* __restrict__ p2w, const float* __restrict__ p2b,
    float* __restrict__ out) {
    __shared__ __align__(16) float sW[TTILE][KK];   // normalized softmax weights
    __shared__ __align__(16) float Csm[KK * 17];    // W-scaled C for current frame (padded)
    __shared__ float sW2[256];                 // sw1_w2 [16,16]
    __shared__ float w1r0[16], w1r1[16], sB2[16];
    __shared__ float s2r0[2], s2r1[2], s2W2[4], s2B2[2], sp1[2];
    __shared__ float sp1b;
    __shared__ float sA[TTILE][16];
    __shared__ float sApart[16][17];
    __shared__ float sRed[8];
    __shared__ float sMax, sInv;

    int tid = threadIdx.x;
    int b = blockIdx.y;
    int t0 = blockIdx.x * TTILE;
    int lane = tid & 31, wid = tid >> 5;

    sW2[tid] = sw1w2[tid];
    if (tid < 16) { w1r0[tid] = sw1w1[tid]; w1r1[tid] = sw1w1[16 + tid]; sB2[tid] = sw1b2[tid]; }
    if (tid < 2)  { s2r0[tid] = sw2w1[tid]; s2r1[tid] = sw2w1[2 + tid]; s2B2[tid] = sw2b2[tid]; sp1[tid] = p1w[tid]; }
    if (tid < 4)  s2W2[tid] = sw2w2[tid];
    if (tid == 0) sp1b = p1b[0];

    float base1[16];
    float base2_0 = 0.f, base2_1 = 0.f, startk = 0.f, endk = 0.f;
    if (tid < KK) {
        startk = g_start[b * KK + tid];
        endk   = g_end[b * KK + tid];
#pragma unroll
        for (int i = 0; i < 16; i++) base1[i] = g_base1[(b * KK + tid) * 16 + i];
        base2_0 = g_base2[(b * KK + tid) * 2 + 0];
        base2_1 = g_base2[(b * KK + tid) * 2 + 1];
    }
    __syncthreads();

    for (int tt = 0; tt < TTILE; tt++) {
        float t = (float)(t0 + tt);
        float S = t - startk, E = endk - t;

        float logit = -1e30f;
        if (tid < KK) {
            float g0  = silu_f(fmaf(S, s2r0[0], fmaf(E, s2r1[0], base2_0)));
            float g1  = silu_f(fmaf(S, s2r0[1], fmaf(E, s2r1[1], base2_1)));
            float rr0 = silu_f(fmaf(g0, s2W2[0], fmaf(g1, s2W2[2], s2B2[0])));
            float rr1 = silu_f(fmaf(g0, s2W2[1], fmaf(g1, s2W2[3], s2B2[1])));
            logit = fmaf(rr0, sp1[0], fmaf(rr1, sp1[1], sp1b));
        }

        // block max
        float v = logit;
#pragma unroll
        for (int o = 16; o; o >>= 1) v = fmaxf(v, __shfl_xor_sync(0xffffffffu, v, o));
        if (lane == 0) sRed[wid] = v;
        __syncthreads();
        if (tid == 0) {
            float m = sRed[0];
#pragma unroll
            for (int i = 1; i < 8; i++) m = fmaxf(m, sRed[i]);
            sMax = m;
        }
        __syncthreads();

        float e = (tid < KK) ? __expf(logit - sMax) : 0.f;
        v = e;
#pragma unroll
        for (int o = 16; o; o >>= 1) v += __shfl_xor_sync(0xffffffffu, v, o);
        if (lane == 0) sRed[wid] = v;
        __syncthreads();
        if (tid == 0) {
            float s = 0.f;
#pragma unroll
            for (int i = 0; i < 8; i++) s += sRed[i];
            sInv = 1.0f / s;
        }
        __syncthreads();

        float wk = e * sInv;
        if (tid < KK) {
            sW[tt][tid] = wk;
            float h1[16];
#pragma unroll
            for (int i = 0; i < 16; i++)
                h1[i] = silu_f(fmaf(S, w1r0[i], fmaf(E, w1r1[i], base1[i])));
#pragma unroll
            for (int j = 0; j < 16; j++) {
                float s = sB2[j];
#pragma unroll
                for (int i = 0; i < 16; i++) s = fmaf(h1[i], sW2[i * 16 + j], s);
                Csm[tid * 17 + j] = wk * silu_f(s);
            }
        }
        __syncthreads();

        // A[p] = sum_k Csm[k][p]  (Csm already W-scaled)
        {
            int p = tid & 15, chunk = tid >> 4;
            float s = 0.f;
            for (int k = chunk; k < KK; k += 16) s += Csm[k * 17 + p];
            sApart[chunk][p] = s;
        }
        __syncthreads();
        if (tid < 16) {
            float s = 0.f;
#pragma unroll
            for (int c = 0; c < 16; c++) s += sApart[c][tid];
            sA[tt][tid] = s;
        }
        __syncthreads();
    }

    // O phase: acc[tt][d] = sum_k W[tt][k] * F[k][d]; each feature load reused 8x
    float acc[TTILE];
#pragma unroll
    for (int tt = 0; tt < TTILE; tt++) acc[tt] = 0.f;

    const float* F = features + b * KK * DIMN + tid;
    for (int k = 0; k < KK; k += 4) {
        float f0 = F[(k + 0) * DIMN];
        float f1 = F[(k + 1) * DIMN];
        float f2 = F[(k + 2) * DIMN];
        float f3 = F[(k + 3) * DIMN];
#pragma unroll
        for (int tt = 0; tt < TTILE; tt++) {
            float4 w4 = *reinterpret_cast<const float4*>(&sW[tt][k]);
            acc[tt] = fmaf(w4.x, f0, acc[tt]);
            acc[tt] = fmaf(w4.y, f1, acc[tt]);
            acc[tt] = fmaf(w4.z, f2, acc[tt]);
            acc[tt] = fmaf(w4.w, f3, acc[tt]);
        }
    }

    float pb = p2b[tid];
#pragma unroll
    for (int tt = 0; tt < TTILE; tt++) {
        float r = acc[tt] + pb;
#pragma unroll
        for (int p = 0; p < 16; p++) r = fmaf(sA[tt][p], p2w[p * DIMN + tid], r);
        out[((b * TFRAMES) + t0 + tt) * DIMN + tid] = r;
    }
}

// ---------------------------------------------------------------------------
extern "C" void kernel_launch(void* const* d_in, const int* in_sizes, int n_in,
                              void* d_out, int out_size) {
    // metadata order: T, durations, features, conv1_w, conv1_b, conv2_w, conv2_b,
    // sw1_w1, sw1_b1, sw1_w2, sw1_b2, sw2_w1, sw2_b1, sw2_w2, sw2_b2,
    // p1_w, p1_b, p2_w, p2_b
    const float* dur      = (const float*)d_in[1];
    const float* features = (const float*)d_in[2];
    const float* c1w      = (const float*)d_in[3];
    const float* c1b      = (const float*)d_in[4];
    const float* c2w      = (const float*)d_in[5];
    const float* c2b      = (const float*)d_in[6];
    const float* sw1w1    = (const float*)d_in[7];
    const float* sw1b1    = (const float*)d_in[8];
    const float* sw1w2    = (const float*)d_in[9];
    const float* sw1b2    = (const float*)d_in[10];
    const float* sw2w1    = (const float*)d_in[11];
    const float* sw2b1    = (const float*)d_in[12];
    const float* sw2w2    = (const float*)d_in[13];
    const float* sw2b2    = (const float*)d_in[14];
    const float* p1w      = (const float*)d_in[15];
    const float* p1b      = (const float*)d_in[16];
    const float* p2w      = (const float*)d_in[17];
    const float* p2b      = (const float*)d_in[18];
    float* out = (float*)d_out;

    cumsum_kernel<<<BB, 32>>>(dur);
    conv_kernel<<<BB * KK, 256>>>(features, c1w, c1b, c2w, c2b,
                                  sw1w1, sw1b1, sw2w1, sw2b1);
    main_kernel<<<dim3(TFRAMES / TTILE, BB), 256>>>(
        features, sw1w1, sw1w2, sw1b2, sw2w1, sw2w2, sw2b2,
        p1w, p1b, p2w, p2b, out);
}

// round 5
// speedup vs baseline: 2.1962x; 2.1962x over previous
#include <cuda_runtime.h>

#define BB 4
#define KK 200
#define DIMN 256
#define TFRAMES 800
#define TTILE 8

// ---- scratch (no allocations allowed) ----
__device__ float g_start[BB * KK];
__device__ float g_end[BB * KK];
__device__ float g_base1[BB * KK * 16];
__device__ float g_base2[BB * KK * 2];

__device__ __forceinline__ float silu_f(float x) {
    return __fdividef(x, 1.0f + __expf(-x));
}

// ---------------------------------------------------------------------------
// Kernel A: blocks 0..99 = conv1d(k=3)+SiLU for 8 tokens each (both branches),
// folding the t-invariant 8 conv features through rows 2..9 of sw1_w1/sw2_w1
// into per-(b,k) base vectors. Block 100 = warp-scan cumsum of durations.
// ---------------------------------------------------------------------------
__global__ __launch_bounds__(256) void prep_kernel(
    const float* __restrict__ dur, const float* __restrict__ features,
    const float* __restrict__ c1w, const float* __restrict__ c1b,
    const float* __restrict__ c2w, const float* __restrict__ c2b,
    const float* __restrict__ sw1w1, const float* __restrict__ sw1b1,
    const float* __restrict__ sw2w1, const float* __restrict__ sw2b1) {
    int tid = threadIdx.x;
    int lane = tid & 31, w = tid >> 5;

    if (blockIdx.x == 100) {
        // durations cumsum: warp b scans 200 values in 7 chunks
        if (w < BB) {
            float carry = 0.f;
            for (int c = 0; c < 7; c++) {
                int idx = c * 32 + lane;
                float d = (idx < KK) ? dur[w * KK + idx] : 0.f;
                float v = d;
#pragma unroll
                for (int o = 1; o < 32; o <<= 1) {
                    float u = __shfl_up_sync(0xffffffffu, v, o);
                    if (lane >= o) v += u;
                }
                if (idx < KK) {
                    g_end[w * KK + idx] = carry + v;
                    g_start[w * KK + idx] = carry + v - d;
                }
                carry += __shfl_sync(0xffffffffu, v, 31);
            }
        }
        return;
    }

    int b = blockIdx.x / 25;
    int k0 = (blockIdx.x % 25) * 8;
    __shared__ float featS[10][256];   // rows k0-1 .. k0+8
    __shared__ float convS[8][16];     // [token][8 left | 8 right]

    for (int i = tid; i < 2560; i += 256) {
        int r = i >> 8, d = i & 255;
        int row = k0 - 1 + r;
        featS[r][d] = (row >= 0 && row < KK) ? features[(b * KK + row) * DIMN + d] : 0.f;
    }
    __syncthreads();

    // warp w computes token k0+w: 16 output channels, lanes partition (j,d)
    float acc[16];
#pragma unroll
    for (int c = 0; c < 16; c++) acc[c] = 0.f;
    for (int it = 0; it < 24; it++) {
        int i = it * 32 + lane;
        int j = i >> 8, d = i & 255;
        float f = featS[w + j][d];
        int off = (j * 256 + d) * 8;          // weights [3,256,8]: w contiguous
        float4 a0 = *reinterpret_cast<const float4*>(c1w + off);
        float4 a1 = *reinterpret_cast<const float4*>(c1w + off + 4);
        float4 b0 = *reinterpret_cast<const float4*>(c2w + off);
        float4 b1 = *reinterpret_cast<const float4*>(c2w + off + 4);
        acc[0] = fmaf(f, a0.x, acc[0]);  acc[1] = fmaf(f, a0.y, acc[1]);
        acc[2] = fmaf(f, a0.z, acc[2]);  acc[3] = fmaf(f, a0.w, acc[3]);
        acc[4] = fmaf(f, a1.x, acc[4]);  acc[5] = fmaf(f, a1.y, acc[5]);
        acc[6] = fmaf(f, a1.z, acc[6]);  acc[7] = fmaf(f, a1.w, acc[7]);
        acc[8]  = fmaf(f, b0.x, acc[8]);  acc[9]  = fmaf(f, b0.y, acc[9]);
        acc[10] = fmaf(f, b0.z, acc[10]); acc[11] = fmaf(f, b0.w, acc[11]);
        acc[12] = fmaf(f, b1.x, acc[12]); acc[13] = fmaf(f, b1.y, acc[13]);
        acc[14] = fmaf(f, b1.z, acc[14]); acc[15] = fmaf(f, b1.w, acc[15]);
    }
#pragma unroll
    for (int c = 0; c < 16; c++) {
        float v = acc[c];
#pragma unroll
        for (int o = 16; o; o >>= 1) v += __shfl_down_sync(0xffffffffu, v, o);
        if (lane == 0) convS[w][c] = v;
    }
    __syncthreads();

    if (tid < 128) {  // bias + SiLU
        int tk = tid >> 4, c = tid & 15;
        float bsl = (c < 8) ? c1b[c] : c2b[c - 8];
        convS[tk][c] = silu_f(convS[tk][c] + bsl);
    }
    __syncthreads();

    if (tid < 128) {  // base1[(b,k)][i] = sw1b1[i] + sum_c left[c]*sw1w1[2+c][i]
        int tk = tid >> 4, i = tid & 15;
        float s = sw1b1[i];
#pragma unroll
        for (int c = 0; c < 8; c++) s = fmaf(convS[tk][c], sw1w1[(2 + c) * 16 + i], s);
        g_base1[(b * KK + k0 + tk) * 16 + i] = s;
    } else if (tid < 144) {
        int t2 = tid - 128, tk = t2 >> 1, j = t2 & 1;
        float s = sw2b1[j];
#pragma unroll
        for (int c = 0; c < 8; c++) s = fmaf(convS[tk][8 + c], sw2w1[(2 + c) * 2 + j], s);
        g_base2[(b * KK + k0 + tk) * 2 + j] = s;
    }
}

// ---------------------------------------------------------------------------
// Kernel B: fused main. One block = (b, 8 frames). Batched logits (1 pass),
// 8 warp-parallel softmax reductions (2 barriers total), C phase in 2-frame
// chunks with tree-reduced A, then one batched O pass reusing feature loads.
// ---------------------------------------------------------------------------
__global__ __launch_bounds__(256) void main_kernel(
    const float* __restrict__ features,
    const float* __restrict__ sw1w1, const float* __restrict__ sw1w2,
    const float* __restrict__ sw1b2,
    const float* __restrict__ sw2w1, const float* __restrict__ sw2w2,
    const float* __restrict__ sw2b2,
    const float* __restrict__ p1w, const float* __restrict__ p1b,
    const float* __restrict__ p2w, const float* __restrict__ p2b,
    float* __restrict__ out) {
    __shared__ __align__(16) float sE[TTILE][KK];      // logits -> e -> W
    __shared__ __align__(16) float Csm[2][KK][17];     // W-scaled C, 2 frames
    __shared__ float sW2s[256];
    __shared__ float w1r0[16], w1r1[16], sB2[16];
    __shared__ float sInv[TTILE];
    __shared__ float sPart[2][16][8];
    __shared__ float sA[TTILE][16];

    int tid = threadIdx.x;
    int b = blockIdx.y;
    int t0 = blockIdx.x * TTILE;
    int lane = tid & 31, wid = tid >> 5;

    sW2s[tid] = sw1w2[tid];
    if (tid < 16) { w1r0[tid] = sw1w1[tid]; w1r1[tid] = sw1w1[16 + tid]; sB2[tid] = sw1b2[tid]; }

    // tiny uniform constants (L1/const cache)
    float s2r00 = sw2w1[0], s2r01 = sw2w1[1];
    float s2r10 = sw2w1[2], s2r11 = sw2w1[3];
    float w20 = sw2w2[0], w21 = sw2w2[1], w22 = sw2w2[2], w23 = sw2w2[3];
    float b20 = sw2b2[0], b21 = sw2b2[1];
    float p10 = p1w[0], p11 = p1w[1], pb1 = p1b[0];

    float base1[16];
    float base2_0 = 0.f, base2_1 = 0.f, startk = 0.f, endk = 0.f;
    if (tid < KK) {
        startk = g_start[b * KK + tid];
        endk   = g_end[b * KK + tid];
#pragma unroll
        for (int i = 0; i < 16; i++) base1[i] = g_base1[(b * KK + tid) * 16 + i];
        base2_0 = g_base2[(b * KK + tid) * 2 + 0];
        base2_1 = g_base2[(b * KK + tid) * 2 + 1];
    }

    // ---- logits for all 8 frames ----
    if (tid < KK) {
#pragma unroll
        for (int tt = 0; tt < TTILE; tt++) {
            float t = (float)(t0 + tt);
            float S = t - startk, E = endk - t;
            float g0  = silu_f(fmaf(S, s2r00, fmaf(E, s2r10, base2_0)));
            float g1  = silu_f(fmaf(S, s2r01, fmaf(E, s2r11, base2_1)));
            float rr0 = silu_f(fmaf(g0, w20, fmaf(g1, w22, b20)));
            float rr1 = silu_f(fmaf(g0, w21, fmaf(g1, w23, b21)));
            sE[tt][tid] = fmaf(rr0, p10, fmaf(rr1, p11, pb1));
        }
    }
    __syncthreads();

    // ---- warp wid reduces frame wid: max, exp in place, sum ----
    {
        float v[7];
        float m = -1e30f;
#pragma unroll
        for (int c = 0; c < 7; c++) {
            int idx = c * 32 + lane;
            v[c] = (idx < KK) ? sE[wid][idx] : -1e30f;
            m = fmaxf(m, v[c]);
        }
#pragma unroll
        for (int o = 16; o; o >>= 1) m = fmaxf(m, __shfl_xor_sync(0xffffffffu, m, o));
        float s = 0.f;
#pragma unroll
        for (int c = 0; c < 7; c++) {
            int idx = c * 32 + lane;
            if (idx < KK) {
                float e = __expf(v[c] - m);
                sE[wid][idx] = e;
                s += e;
            }
        }
#pragma unroll
        for (int o = 16; o; o >>= 1) s += __shfl_xor_sync(0xffffffffu, s, o);
        if (lane == 0) sInv[wid] = 1.0f / s;
    }
    __syncthreads();

    float inv[TTILE];
#pragma unroll
    for (int tt = 0; tt < TTILE; tt++) inv[tt] = sInv[tt];

    // ---- C phase + A reduction, 2 frames per chunk ----
    for (int half = 0; half < 4; half++) {
        if (tid < KK) {
#pragma unroll
            for (int u = 0; u < 2; u++) {
                int tt = half * 2 + u;
                float t = (float)(t0 + tt);
                float S = t - startk, E = endk - t;
                float wk = sE[tt][tid] * inv[tt];
                sE[tt][tid] = wk;                     // normalized in place
                float h1[16];
#pragma unroll
                for (int i = 0; i < 16; i++)
                    h1[i] = silu_f(fmaf(S, w1r0[i], fmaf(E, w1r1[i], base1[i])));
#pragma unroll
                for (int j = 0; j < 16; j++) {
                    float s = sB2[j];
#pragma unroll
                    for (int i = 0; i < 16; i++) s = fmaf(h1[i], sW2s[i * 16 + j], s);
                    Csm[u][tid][j] = wk * silu_f(s);
                }
            }
        }
        __syncthreads();
        {   // stage 1: 256 threads = (u, p, chunk-of-25)
            int u = tid >> 7, p = (tid >> 3) & 15, ch = tid & 7;
            float s = 0.f;
            int kbeg = ch * 25;
            for (int k = kbeg; k < kbeg + 25; k++) s += Csm[u][k][p];
            sPart[u][p][ch] = s;
        }
        __syncthreads();
        if (tid < 32) {  // stage 2
            int u = tid >> 4, p = tid & 15;
            float s = 0.f;
#pragma unroll
            for (int ch = 0; ch < 8; ch++) s += sPart[u][p][ch];
            sA[half * 2 + u][p] = s;
        }
        __syncthreads();
    }

    // ---- O phase: acc[tt][d] = sum_k W[tt][k]*F[k][d], feature loads reused 8x
    float acc[TTILE];
#pragma unroll
    for (int tt = 0; tt < TTILE; tt++) acc[tt] = 0.f;

    const float* F = features + b * KK * DIMN + tid;
    for (int k = 0; k < KK; k += 4) {
        float f0 = F[(k + 0) * DIMN];
        float f1 = F[(k + 1) * DIMN];
        float f2 = F[(k + 2) * DIMN];
        float f3 = F[(k + 3) * DIMN];
#pragma unroll
        for (int tt = 0; tt < TTILE; tt++) {
            float4 w4 = *reinterpret_cast<const float4*>(&sE[tt][k]);
            acc[tt] = fmaf(w4.x, f0, acc[tt]);
            acc[tt] = fmaf(w4.y, f1, acc[tt]);
            acc[tt] = fmaf(w4.z, f2, acc[tt]);
            acc[tt] = fmaf(w4.w, f3, acc[tt]);
        }
    }

    float pb = p2b[tid];
#pragma unroll
    for (int tt = 0; tt < TTILE; tt++) {
        float r = acc[tt] + pb;
#pragma unroll
        for (int p = 0; p < 16; p++) r = fmaf(sA[tt][p], p2w[p * DIMN + tid], r);
        out[((b * TFRAMES) + t0 + tt) * DIMN + tid] = r;
    }
}

// ---------------------------------------------------------------------------
extern "C" void kernel_launch(void* const* d_in, const int* in_sizes, int n_in,
                              void* d_out, int out_size) {
    const float* dur      = (const float*)d_in[1];
    const float* features = (const float*)d_in[2];
    const float* c1w      = (const float*)d_in[3];
    const float* c1b      = (const float*)d_in[4];
    const float* c2w      = (const float*)d_in[5];
    const float* c2b      = (const float*)d_in[6];
    const float* sw1w1    = (const float*)d_in[7];
    const float* sw1b1    = (const float*)d_in[8];
    const float* sw1w2    = (const float*)d_in[9];
    const float* sw1b2    = (const float*)d_in[10];
    const float* sw2w1    = (const float*)d_in[11];
    const float* sw2b1    = (const float*)d_in[12];
    const float* sw2w2    = (const float*)d_in[13];
    const float* sw2b2    = (const float*)d_in[14];
    const float* p1w      = (const float*)d_in[15];
    const float* p1b      = (const float*)d_in[16];
    const float* p2w      = (const float*)d_in[17];
    const float* p2b      = (const float*)d_in[18];
    float* out = (float*)d_out;

    prep_kernel<<<101, 256>>>(dur, features, c1w, c1b, c2w, c2b,
                              sw1w1, sw1b1, sw2w1, sw2b1);
    main_kernel<<<dim3(TFRAMES / TTILE, BB), 256>>>(
        features, sw1w1, sw1w2, sw1b2, sw2w1, sw2w2, sw2b2,
        p1w, p1b, p2w, p2b, out);
}

// round 6
// speedup vs baseline: 2.3035x; 1.0489x over previous
#include <cuda_runtime.h>

#define BB 4
#define KK 200
#define DIMN 256
#define TFRAMES 800
#define TTILE 8

// ---- scratch (no allocations allowed) ----
__device__ float g_start[BB * KK];
__device__ float g_end[BB * KK];
__device__ float g_base1[BB * KK * 16];
__device__ float g_base2[BB * KK * 2];

__device__ __forceinline__ float silu_f(float x) {
    return __fdividef(x, 1.0f + __expf(-x));
}

// ---------------------------------------------------------------------------
// Kernel A: blocks 0..99 = conv1d(k=3)+SiLU for 8 tokens each (both branches),
// folding the t-invariant 8 conv features through rows 2..9 of sw1_w1/sw2_w1
// into per-(b,k) base vectors. Block 100 = warp-scan cumsum of durations.
// ---------------------------------------------------------------------------
__global__ __launch_bounds__(256) void prep_kernel(
    const float* __restrict__ dur, const float* __restrict__ features,
    const float* __restrict__ c1w, const float* __restrict__ c1b,
    const float* __restrict__ c2w, const float* __restrict__ c2b,
    const float* __restrict__ sw1w1, const float* __restrict__ sw1b1,
    const float* __restrict__ sw2w1, const float* __restrict__ sw2b1) {
    int tid = threadIdx.x;
    int lane = tid & 31, w = tid >> 5;

    if (blockIdx.x == 100) {
        if (w < BB) {
            float carry = 0.f;
            for (int c = 0; c < 7; c++) {
                int idx = c * 32 + lane;
                float d = (idx < KK) ? dur[w * KK + idx] : 0.f;
                float v = d;
#pragma unroll
                for (int o = 1; o < 32; o <<= 1) {
                    float u = __shfl_up_sync(0xffffffffu, v, o);
                    if (lane >= o) v += u;
                }
                if (idx < KK) {
                    g_end[w * KK + idx] = carry + v;
                    g_start[w * KK + idx] = carry + v - d;
                }
                carry += __shfl_sync(0xffffffffu, v, 31);
            }
        }
        return;
    }

    int b = blockIdx.x / 25;
    int k0 = (blockIdx.x % 25) * 8;
    __shared__ float featS[10][256];   // rows k0-1 .. k0+8
    __shared__ float convS[8][16];     // [token][8 left | 8 right]

    for (int i = tid; i < 2560; i += 256) {
        int r = i >> 8, d = i & 255;
        int row = k0 - 1 + r;
        featS[r][d] = (row >= 0 && row < KK) ? features[(b * KK + row) * DIMN + d] : 0.f;
    }
    __syncthreads();

    float acc[16];
#pragma unroll
    for (int c = 0; c < 16; c++) acc[c] = 0.f;
    for (int it = 0; it < 24; it++) {
        int i = it * 32 + lane;
        int j = i >> 8, d = i & 255;
        float f = featS[w + j][d];
        int off = (j * 256 + d) * 8;          // weights [3,256,8]: w contiguous
        float4 a0 = *reinterpret_cast<const float4*>(c1w + off);
        float4 a1 = *reinterpret_cast<const float4*>(c1w + off + 4);
        float4 b0 = *reinterpret_cast<const float4*>(c2w + off);
        float4 b1 = *reinterpret_cast<const float4*>(c2w + off + 4);
        acc[0] = fmaf(f, a0.x, acc[0]);  acc[1] = fmaf(f, a0.y, acc[1]);
        acc[2] = fmaf(f, a0.z, acc[2]);  acc[3] = fmaf(f, a0.w, acc[3]);
        acc[4] = fmaf(f, a1.x, acc[4]);  acc[5] = fmaf(f, a1.y, acc[5]);
        acc[6] = fmaf(f, a1.z, acc[6]);  acc[7] = fmaf(f, a1.w, acc[7]);
        acc[8]  = fmaf(f, b0.x, acc[8]);  acc[9]  = fmaf(f, b0.y, acc[9]);
        acc[10] = fmaf(f, b0.z, acc[10]); acc[11] = fmaf(f, b0.w, acc[11]);
        acc[12] = fmaf(f, b1.x, acc[12]); acc[13] = fmaf(f, b1.y, acc[13]);
        acc[14] = fmaf(f, b1.z, acc[14]); acc[15] = fmaf(f, b1.w, acc[15]);
    }
#pragma unroll
    for (int c = 0; c < 16; c++) {
        float v = acc[c];
#pragma unroll
        for (int o = 16; o; o >>= 1) v += __shfl_down_sync(0xffffffffu, v, o);
        if (lane == 0) convS[w][c] = v;
    }
    __syncthreads();

    if (tid < 128) {
        int tk = tid >> 4, c = tid & 15;
        float bsl = (c < 8) ? c1b[c] : c2b[c - 8];
        convS[tk][c] = silu_f(convS[tk][c] + bsl);
    }
    __syncthreads();

    if (tid < 128) {
        int tk = tid >> 4, i = tid & 15;
        float s = sw1b1[i];
#pragma unroll
        for (int c = 0; c < 8; c++) s = fmaf(convS[tk][c], sw1w1[(2 + c) * 16 + i], s);
        g_base1[(b * KK + k0 + tk) * 16 + i] = s;
    } else if (tid < 144) {
        int t2 = tid - 128, tk = t2 >> 1, j = t2 & 1;
        float s = sw2b1[j];
#pragma unroll
        for (int c = 0; c < 8; c++) s = fmaf(convS[tk][8 + c], sw2w1[(2 + c) * 2 + j], s);
        g_base2[(b * KK + k0 + tk) * 2 + j] = s;
    }
}

// ---------------------------------------------------------------------------
// Kernel B: fused main. One block = (b, 8 frames).
//   logits (k-parallel, batched) -> 8 warp-parallel softmax (normalize in-warp)
//   per frame: h1 -> smem, then (p, chunk) threads hold W2 column p in regs and
//   accumulate A locally (C never materialized), tiny 16x16 reduce.
//   Then one batched O pass reusing each feature load across all 8 frames.
// ---------------------------------------------------------------------------
__global__ __launch_bounds__(256, 3) void main_kernel(
    const float* __restrict__ features,
    const float* __restrict__ sw1w1, const float* __restrict__ sw1w2,
    const float* __restrict__ sw1b2,
    const float* __restrict__ sw2w1, const float* __restrict__ sw2w2,
    const float* __restrict__ sw2b2,
    const float* __restrict__ p1w, const float* __restrict__ p1b,
    const float* __restrict__ p2w, const float* __restrict__ p2b,
    float* __restrict__ out) {
    __shared__ __align__(16) float sE[TTILE][KK];   // logits -> normalized W
    __shared__ __align__(16) float sH1[KK * 16];    // h1 for current frame
    __shared__ __align__(16) float sB1[KK * 16];    // base1 staged
    __shared__ float w1r0[16], w1r1[16];
    __shared__ float sPart[16][17];
    __shared__ float sA[TTILE][16];

    int tid = threadIdx.x;
    int b = blockIdx.y;
    int t0 = blockIdx.x * TTILE;
    int lane = tid & 31, wid = tid >> 5;

    if (tid < 16) { w1r0[tid] = sw1w1[tid]; w1r1[tid] = sw1w1[16 + tid]; }

    // stage base1 into smem (coalesced)
    for (int i = tid; i < KK * 16; i += 256) sB1[i] = g_base1[b * KK * 16 + i];

    // W2 column for this thread's p-slot (A phase), plus bias
    int p = tid & 15, chunk = tid >> 4;
    float w2c[16];
#pragma unroll
    for (int i = 0; i < 16; i++) w2c[i] = sw1w2[i * 16 + p];
    float b2p = sw1b2[p];

    // tiny uniform constants
    float s2r00 = sw2w1[0], s2r01 = sw2w1[1];
    float s2r10 = sw2w1[2], s2r11 = sw2w1[3];
    float w20 = sw2w2[0], w21 = sw2w2[1], w22 = sw2w2[2], w23 = sw2w2[3];
    float b20 = sw2b2[0], b21 = sw2b2[1];
    float p10 = p1w[0], p11 = p1w[1], pb1 = p1b[0];

    float base2_0 = 0.f, base2_1 = 0.f, startk = 0.f, endk = 0.f;
    if (tid < KK) {
        startk = g_start[b * KK + tid];
        endk   = g_end[b * KK + tid];
        base2_0 = g_base2[(b * KK + tid) * 2 + 0];
        base2_1 = g_base2[(b * KK + tid) * 2 + 1];
    }

    // ---- logits for all 8 frames ----
    if (tid < KK) {
#pragma unroll
        for (int tt = 0; tt < TTILE; tt++) {
            float t = (float)(t0 + tt);
            float S = t - startk, E = endk - t;
            float g0  = silu_f(fmaf(S, s2r00, fmaf(E, s2r10, base2_0)));
            float g1  = silu_f(fmaf(S, s2r01, fmaf(E, s2r11, base2_1)));
            float rr0 = silu_f(fmaf(g0, w20, fmaf(g1, w22, b20)));
            float rr1 = silu_f(fmaf(g0, w21, fmaf(g1, w23, b21)));
            sE[tt][tid] = fmaf(rr0, p10, fmaf(rr1, p11, pb1));
        }
    }
    __syncthreads();

    // ---- warp wid: softmax of frame wid, normalized in place ----
    {
        float v[7];
        float m = -1e30f;
#pragma unroll
        for (int c = 0; c < 7; c++) {
            int idx = c * 32 + lane;
            v[c] = (idx < KK) ? sE[wid][idx] : -1e30f;
            m = fmaxf(m, v[c]);
        }
#pragma unroll
        for (int o = 16; o; o >>= 1) m = fmaxf(m, __shfl_xor_sync(0xffffffffu, m, o));
        float s = 0.f;
#pragma unroll
        for (int c = 0; c < 7; c++) {
            v[c] = __expf(v[c] - m);
            if (c * 32 + lane < KK) s += v[c];
        }
#pragma unroll
        for (int o = 16; o; o >>= 1) s += __shfl_xor_sync(0xffffffffu, s, o);
        float invs = 1.0f / s;
#pragma unroll
        for (int c = 0; c < 7; c++) {
            int idx = c * 32 + lane;
            if (idx < KK) sE[wid][idx] = v[c] * invs;
        }
    }
    __syncthreads();

    // ---- per frame: h1 -> smem, then register-W2 A accumulation ----
    for (int tt = 0; tt < TTILE; tt++) {
        if (tid < KK) {
            float t = (float)(t0 + tt);
            float S = t - startk, E = endk - t;
#pragma unroll
            for (int q = 0; q < 4; q++) {
                float4 bq = *reinterpret_cast<const float4*>(&sB1[tid * 16 + q * 4]);
                float4 h;
                h.x = silu_f(fmaf(S, w1r0[q * 4 + 0], fmaf(E, w1r1[q * 4 + 0], bq.x)));
                h.y = silu_f(fmaf(S, w1r0[q * 4 + 1], fmaf(E, w1r1[q * 4 + 1], bq.y)));
                h.z = silu_f(fmaf(S, w1r0[q * 4 + 2], fmaf(E, w1r1[q * 4 + 2], bq.z)));
                h.w = silu_f(fmaf(S, w1r0[q * 4 + 3], fmaf(E, w1r1[q * 4 + 3], bq.w)));
                *reinterpret_cast<float4*>(&sH1[tid * 16 + q * 4]) = h;
            }
        }
        __syncthreads();

        float accA = 0.f;
        for (int k = chunk; k < KK; k += 16) {
            const float4* hp = reinterpret_cast<const float4*>(&sH1[k * 16]);
            float4 h0 = hp[0], h1v = hp[1], h2 = hp[2], h3 = hp[3];
            float s = b2p;
            s = fmaf(h0.x, w2c[0], s);  s = fmaf(h0.y, w2c[1], s);
            s = fmaf(h0.z, w2c[2], s);  s = fmaf(h0.w, w2c[3], s);
            s = fmaf(h1v.x, w2c[4], s); s = fmaf(h1v.y, w2c[5], s);
            s = fmaf(h1v.z, w2c[6], s); s = fmaf(h1v.w, w2c[7], s);
            s = fmaf(h2.x, w2c[8], s);  s = fmaf(h2.y, w2c[9], s);
            s = fmaf(h2.z, w2c[10], s); s = fmaf(h2.w, w2c[11], s);
            s = fmaf(h3.x, w2c[12], s); s = fmaf(h3.y, w2c[13], s);
            s = fmaf(h3.z, w2c[14], s); s = fmaf(h3.w, w2c[15], s);
            accA = fmaf(sE[tt][k], silu_f(s), accA);
        }
        sPart[chunk][p] = accA;
        __syncthreads();

        if (tid < 16) {
            float s = 0.f;
#pragma unroll
            for (int c = 0; c < 16; c++) s += sPart[c][tid];
            sA[tt][tid] = s;
        }
        // next iteration's B1 barrier protects sPart/sA; final read protected below
    }
    __syncthreads();

    // ---- O phase: acc[tt][d] = sum_k W[tt][k]*F[k][d], feature loads reused 8x
    float acc[TTILE];
#pragma unroll
    for (int tt = 0; tt < TTILE; tt++) acc[tt] = 0.f;

    const float* F = features + b * KK * DIMN + tid;
    for (int k = 0; k < KK; k += 4) {
        float f0 = F[(k + 0) * DIMN];
        float f1 = F[(k + 1) * DIMN];
        float f2 = F[(k + 2) * DIMN];
        float f3 = F[(k + 3) * DIMN];
#pragma unroll
        for (int tt = 0; tt < TTILE; tt++) {
            float4 w4 = *reinterpret_cast<const float4*>(&sE[tt][k]);
            acc[tt] = fmaf(w4.x, f0, acc[tt]);
            acc[tt] = fmaf(w4.y, f1, acc[tt]);
            acc[tt] = fmaf(w4.z, f2, acc[tt]);
            acc[tt] = fmaf(w4.w, f3, acc[tt]);
        }
    }

    float p2wr[16];
#pragma unroll
    for (int q = 0; q < 16; q++) p2wr[q] = p2w[q * DIMN + tid];
    float pb = p2b[tid];
#pragma unroll
    for (int tt = 0; tt < TTILE; tt++) {
        float r = acc[tt] + pb;
#pragma unroll
        for (int q = 0; q < 16; q++) r = fmaf(sA[tt][q], p2wr[q], r);
        out[((b * TFRAMES) + t0 + tt) * DIMN + tid] = r;
    }
}

// ---------------------------------------------------------------------------
extern "C" void kernel_launch(void* const* d_in, const int* in_sizes, int n_in,
                              void* d_out, int out_size) {
    const float* dur      = (const float*)d_in[1];
    const float* features = (const float*)d_in[2];
    const float* c1w      = (const float*)d_in[3];
    const float* c1b      = (const float*)d_in[4];
    const float* c2w      = (const float*)d_in[5];
    const float* c2b      = (const float*)d_in[6];
    const float* sw1w1    = (const float*)d_in[7];
    const float* sw1b1    = (const float*)d_in[8];
    const float* sw1w2    = (const float*)d_in[9];
    const float* sw1b2    = (const float*)d_in[10];
    const float* sw2w1    = (const float*)d_in[11];
    const float* sw2b1    = (const float*)d_in[12];
    const float* sw2w2    = (const float*)d_in[13];
    const float* sw2b2    = (const float*)d_in[14];
    const float* p1w      = (const float*)d_in[15];
    const float* p1b      = (const float*)d_in[16];
    const float* p2w      = (const float*)d_in[17];
    const float* p2b      = (const float*)d_in[18];
    float* out = (float*)d_out;

    prep_kernel<<<101, 256>>>(dur, features, c1w, c1b, c2w, c2b,
                              sw1w1, sw1b1, sw2w1, sw2b1);
    main_kernel<<<dim3(TFRAMES / TTILE, BB), 256>>>(
        features, sw1w1, sw1w2, sw1b2, sw2w1, sw2w2, sw2b2,
        p1w, p1b, p2w, p2b, out);
}

// round 7
// speedup vs baseline: 2.5648x; 1.1134x over previous
#include <cuda_runtime.h>

#define BB 4
#define KK 200
#define DIMN 256
#define TFRAMES 800
#define TTILE 8

// ---- scratch (no allocations allowed) ----
__device__ float g_start[BB * KK];
__device__ float g_end[BB * KK];
__device__ float g_base1[BB * KK * 16];
__device__ float g_base2[BB * KK * 2];

__device__ __forceinline__ float silu_f(float x) {
    return __fdividef(x, 1.0f + __expf(-x));
}

// ---------------------------------------------------------------------------
// Kernel A: blocks 0..99 = conv1d(k=3)+SiLU for 8 tokens each (both branches),
// folding the t-invariant 8 conv features through rows 2..9 of sw1_w1/sw2_w1
// into per-(b,k) base vectors. Block 100 = warp-scan cumsum of durations.
// ---------------------------------------------------------------------------
__global__ __launch_bounds__(256) void prep_kernel(
    const float* __restrict__ dur, const float* __restrict__ features,
    const float* __restrict__ c1w, const float* __restrict__ c1b,
    const float* __restrict__ c2w, const float* __restrict__ c2b,
    const float* __restrict__ sw1w1, const float* __restrict__ sw1b1,
    const float* __restrict__ sw2w1, const float* __restrict__ sw2b1) {
    int tid = threadIdx.x;
    int lane = tid & 31, w = tid >> 5;

    if (blockIdx.x == 100) {
        if (w < BB) {
            float carry = 0.f;
            for (int c = 0; c < 7; c++) {
                int idx = c * 32 + lane;
                float d = (idx < KK) ? dur[w * KK + idx] : 0.f;
                float v = d;
#pragma unroll
                for (int o = 1; o < 32; o <<= 1) {
                    float u = __shfl_up_sync(0xffffffffu, v, o);
                    if (lane >= o) v += u;
                }
                if (idx < KK) {
                    g_end[w * KK + idx] = carry + v;
                    g_start[w * KK + idx] = carry + v - d;
                }
                carry += __shfl_sync(0xffffffffu, v, 31);
            }
        }
        return;
    }

    int b = blockIdx.x / 25;
    int k0 = (blockIdx.x % 25) * 8;
    __shared__ float featS[10][256];   // rows k0-1 .. k0+8
    __shared__ float convS[8][16];     // [token][8 left | 8 right]

    for (int i = tid; i < 2560; i += 256) {
        int r = i >> 8, d = i & 255;
        int row = k0 - 1 + r;
        featS[r][d] = (row >= 0 && row < KK) ? features[(b * KK + row) * DIMN + d] : 0.f;
    }
    __syncthreads();

    float acc[16];
#pragma unroll
    for (int c = 0; c < 16; c++) acc[c] = 0.f;
    for (int it = 0; it < 24; it++) {
        int i = it * 32 + lane;
        int j = i >> 8, d = i & 255;
        float f = featS[w + j][d];
        int off = (j * 256 + d) * 8;          // weights [3,256,8]: w contiguous
        float4 a0 = *reinterpret_cast<const float4*>(c1w + off);
        float4 a1 = *reinterpret_cast<const float4*>(c1w + off + 4);
        float4 b0 = *reinterpret_cast<const float4*>(c2w + off);
        float4 b1 = *reinterpret_cast<const float4*>(c2w + off + 4);
        acc[0] = fmaf(f, a0.x, acc[0]);  acc[1] = fmaf(f, a0.y, acc[1]);
        acc[2] = fmaf(f, a0.z, acc[2]);  acc[3] = fmaf(f, a0.w, acc[3]);
        acc[4] = fmaf(f, a1.x, acc[4]);  acc[5] = fmaf(f, a1.y, acc[5]);
        acc[6] = fmaf(f, a1.z, acc[6]);  acc[7] = fmaf(f, a1.w, acc[7]);
        acc[8]  = fmaf(f, b0.x, acc[8]);  acc[9]  = fmaf(f, b0.y, acc[9]);
        acc[10] = fmaf(f, b0.z, acc[10]); acc[11] = fmaf(f, b0.w, acc[11]);
        acc[12] = fmaf(f, b1.x, acc[12]); acc[13] = fmaf(f, b1.y, acc[13]);
        acc[14] = fmaf(f, b1.z, acc[14]); acc[15] = fmaf(f, b1.w, acc[15]);
    }
#pragma unroll
    for (int c = 0; c < 16; c++) {
        float v = acc[c];
#pragma unroll
        for (int o = 16; o; o >>= 1) v += __shfl_down_sync(0xffffffffu, v, o);
        if (lane == 0) convS[w][c] = v;
    }
    __syncthreads();

    if (tid < 128) {
        int tk = tid >> 4, c = tid & 15;
        float bsl = (c < 8) ? c1b[c] : c2b[c - 8];
        convS[tk][c] = silu_f(convS[tk][c] + bsl);
    }
    __syncthreads();

    if (tid < 128) {
        int tk = tid >> 4, i = tid & 15;
        float s = sw1b1[i];
#pragma unroll
        for (int c = 0; c < 8; c++) s = fmaf(convS[tk][c], sw1w1[(2 + c) * 16 + i], s);
        g_base1[(b * KK + k0 + tk) * 16 + i] = s;
    } else if (tid < 144) {
        int t2 = tid - 128, tk = t2 >> 1, j = t2 & 1;
        float s = sw2b1[j];
#pragma unroll
        for (int c = 0; c < 8; c++) s = fmaf(convS[tk][8 + c], sw2w1[(2 + c) * 2 + j], s);
        g_base2[(b * KK + k0 + tk) * 2 + j] = s;
    }
}

// ---------------------------------------------------------------------------
// Kernel B: fused main. One block = (b, 8 frames).
//   logits (k-parallel) -> 8 warp-parallel softmax
//   C phase: thread-owns-k; h1 in REGISTERS, W2 read as warp-uniform float4
//   broadcast LDS; W-scaled C rows stored with 4 conflict-free STS.128
//   (row pad 20), then 2-frame tree reduction to A.
//   Then one batched O pass reusing each feature load across all 8 frames.
// ---------------------------------------------------------------------------
__global__ __launch_bounds__(256, 3) void main_kernel(
    const float* __restrict__ features,
    const float* __restrict__ sw1w1, const float* __restrict__ sw1w2,
    const float* __restrict__ sw1b2,
    const float* __restrict__ sw2w1, const float* __restrict__ sw2w2,
    const float* __restrict__ sw2b2,
    const float* __restrict__ p1w, const float* __restrict__ p1b,
    const float* __restrict__ p2w, const float* __restrict__ p2b,
    float* __restrict__ out) {
    __shared__ __align__(16) float sE[TTILE][KK];    // logits -> normalized W
    __shared__ __align__(16) float Csm[2][KK][20];   // W-scaled C, pad 20 (16B-aligned rows)
    __shared__ __align__(16) float sW2s[256];        // sw1_w2 [16,16]
    __shared__ float w1r0[16], w1r1[16], sB2[16];
    __shared__ float sPart[2][16][8];
    __shared__ float sA[TTILE][16];

    int tid = threadIdx.x;
    int b = blockIdx.y;
    int t0 = blockIdx.x * TTILE;
    int lane = tid & 31, wid = tid >> 5;

    sW2s[tid] = sw1w2[tid];
    if (tid < 16) { w1r0[tid] = sw1w1[tid]; w1r1[tid] = sw1w1[16 + tid]; sB2[tid] = sw1b2[tid]; }

    // tiny uniform constants
    float s2r00 = sw2w1[0], s2r01 = sw2w1[1];
    float s2r10 = sw2w1[2], s2r11 = sw2w1[3];
    float w20 = sw2w2[0], w21 = sw2w2[1], w22 = sw2w2[2], w23 = sw2w2[3];
    float b20 = sw2b2[0], b21 = sw2b2[1];
    float p10 = p1w[0], p11 = p1w[1], pb1 = p1b[0];

    // per-k state in registers (tid < 200)
    float base1[16];
    float base2_0 = 0.f, base2_1 = 0.f, startk = 0.f, endk = 0.f;
    if (tid < KK) {
        startk = g_start[b * KK + tid];
        endk   = g_end[b * KK + tid];
        const float4* bp = reinterpret_cast<const float4*>(g_base1 + (b * KK + tid) * 16);
#pragma unroll
        for (int q = 0; q < 4; q++) {
            float4 v = bp[q];
            base1[q * 4 + 0] = v.x; base1[q * 4 + 1] = v.y;
            base1[q * 4 + 2] = v.z; base1[q * 4 + 3] = v.w;
        }
        base2_0 = g_base2[(b * KK + tid) * 2 + 0];
        base2_1 = g_base2[(b * KK + tid) * 2 + 1];
    }

    // ---- logits for all 8 frames ----
    if (tid < KK) {
#pragma unroll
        for (int tt = 0; tt < TTILE; tt++) {
            float t = (float)(t0 + tt);
            float S = t - startk, E = endk - t;
            float g0  = silu_f(fmaf(S, s2r00, fmaf(E, s2r10, base2_0)));
            float g1  = silu_f(fmaf(S, s2r01, fmaf(E, s2r11, base2_1)));
            float rr0 = silu_f(fmaf(g0, w20, fmaf(g1, w22, b20)));
            float rr1 = silu_f(fmaf(g0, w21, fmaf(g1, w23, b21)));
            sE[tt][tid] = fmaf(rr0, p10, fmaf(rr1, p11, pb1));
        }
    }
    __syncthreads();

    // ---- warp wid: softmax of frame wid, normalized in place ----
    {
        float v[7];
        float m = -1e30f;
#pragma unroll
        for (int c = 0; c < 7; c++) {
            int idx = c * 32 + lane;
            v[c] = (idx < KK) ? sE[wid][idx] : -1e30f;
            m = fmaxf(m, v[c]);
        }
#pragma unroll
        for (int o = 16; o; o >>= 1) m = fmaxf(m, __shfl_xor_sync(0xffffffffu, m, o));
        float s = 0.f;
#pragma unroll
        for (int c = 0; c < 7; c++) {
            v[c] = __expf(v[c] - m);
            if (c * 32 + lane < KK) s += v[c];
        }
#pragma unroll
        for (int o = 16; o; o >>= 1) s += __shfl_xor_sync(0xffffffffu, s, o);
        float invs = 1.0f / s;
#pragma unroll
        for (int c = 0; c < 7; c++) {
            int idx = c * 32 + lane;
            if (idx < KK) sE[wid][idx] = v[c] * invs;
        }
    }
    __syncthreads();

    // ---- C phase + A reduction, 2 frames per chunk ----
    const float4* w2v = reinterpret_cast<const float4*>(sW2s);
    for (int half = 0; half < 4; half++) {
        if (tid < KK) {
#pragma unroll
            for (int u = 0; u < 2; u++) {
                int tt = half * 2 + u;
                float t = (float)(t0 + tt);
                float S = t - startk, E = endk - t;
                float wk = sE[tt][tid];
                float h[16];
#pragma unroll
                for (int i = 0; i < 16; i++)
                    h[i] = silu_f(fmaf(S, w1r0[i], fmaf(E, w1r1[i], base1[i])));
#pragma unroll
                for (int jq = 0; jq < 4; jq++) {
                    float s0 = sB2[jq * 4 + 0], s1 = sB2[jq * 4 + 1];
                    float s2 = sB2[jq * 4 + 2], s3 = sB2[jq * 4 + 3];
#pragma unroll
                    for (int i = 0; i < 16; i++) {
                        float4 wv = w2v[i * 4 + jq];   // warp-uniform broadcast LDS.128
                        s0 = fmaf(h[i], wv.x, s0);
                        s1 = fmaf(h[i], wv.y, s1);
                        s2 = fmaf(h[i], wv.z, s2);
                        s3 = fmaf(h[i], wv.w, s3);
                    }
                    float4 c4;
                    c4.x = wk * silu_f(s0);
                    c4.y = wk * silu_f(s1);
                    c4.z = wk * silu_f(s2);
                    c4.w = wk * silu_f(s3);
                    *reinterpret_cast<float4*>(&Csm[u][tid][jq * 4]) = c4;
                }
            }
        }
        __syncthreads();
        {   // stage 1: (u, p, ch-of-25); conflict-free (pad 20)
            int u = tid >> 7, p = (tid >> 3) & 15, ch = tid & 7;
            float s = 0.f;
            int kbeg = ch * 25;
            for (int k = kbeg; k < kbeg + 25; k++) s += Csm[u][k][p];
            sPart[u][p][ch] = s;
        }
        __syncthreads();
        if (tid < 32) {  // stage 2
            int u = tid >> 4, p = tid & 15;
            float s = 0.f;
#pragma unroll
            for (int ch = 0; ch < 8; ch++) s += sPart[u][p][ch];
            sA[half * 2 + u][p] = s;
        }
        __syncthreads();
    }

    // ---- O phase: acc[tt][d] = sum_k W[tt][k]*F[k][d], feature loads reused 8x
    float acc[TTILE];
#pragma unroll
    for (int tt = 0; tt < TTILE; tt++) acc[tt] = 0.f;

    const float* F = features + b * KK * DIMN + tid;
    for (int k = 0; k < KK; k += 4) {
        float f0 = F[(k + 0) * DIMN];
        float f1 = F[(k + 1) * DIMN];
        float f2 = F[(k + 2) * DIMN];
        float f3 = F[(k + 3) * DIMN];
#pragma unroll
        for (int tt = 0; tt < TTILE; tt++) {
            float4 w4 = *reinterpret_cast<const float4*>(&sE[tt][k]);
            acc[tt] = fmaf(w4.x, f0, acc[tt]);
            acc[tt] = fmaf(w4.y, f1, acc[tt]);
            acc[tt] = fmaf(w4.z, f2, acc[tt]);
            acc[tt] = fmaf(w4.w, f3, acc[tt]);
        }
    }

    float p2wr[16];
#pragma unroll
    for (int q = 0; q < 16; q++) p2wr[q] = p2w[q * DIMN + tid];
    float pb = p2b[tid];
#pragma unroll
    for (int tt = 0; tt < TTILE; tt++) {
        float r = acc[tt] + pb;
#pragma unroll
        for (int q = 0; q < 16; q++) r = fmaf(sA[tt][q], p2wr[q], r);
        out[((b * TFRAMES) + t0 + tt) * DIMN + tid] = r;
    }
}

// ---------------------------------------------------------------------------
extern "C" void kernel_launch(void* const* d_in, const int* in_sizes, int n_in,
                              void* d_out, int out_size) {
    const float* dur      = (const float*)d_in[1];
    const float* features = (const float*)d_in[2];
    const float* c1w      = (const float*)d_in[3];
    const float* c1b      = (const float*)d_in[4];
    const float* c2w      = (const float*)d_in[5];
    const float* c2b      = (const float*)d_in[6];
    const float* sw1w1    = (const float*)d_in[7];
    const float* sw1b1    = (const float*)d_in[8];
    const float* sw1w2    = (const float*)d_in[9];
    const float* sw1b2    = (const float*)d_in[10];
    const float* sw2w1    = (const float*)d_in[11];
    const float* sw2b1    = (const float*)d_in[12];
    const float* sw2w2    = (const float*)d_in[13];
    const float* sw2b2    = (const float*)d_in[14];
    const float* p1w      = (const float*)d_in[15];
    const float* p1b      = (const float*)d_in[16];
    const float* p2w      = (const float*)d_in[17];
    const float* p2b      = (const float*)d_in[18];
    float* out = (float*)d_out;

    prep_kernel<<<101, 256>>>(dur, features, c1w, c1b, c2w, c2b,
                              sw1w1, sw1b1, sw2w1, sw2b1);
    main_kernel<<<dim3(TFRAMES / TTILE, BB), 256>>>(
        features, sw1w1, sw1w2, sw1b2, sw2w1, sw2w2, sw2b2,
        p1w, p1b, p2w, p2b, out);
}

// round 9
// speedup vs baseline: 2.9100x; 1.1346x over previous
#include <cuda_runtime.h>

#define BB 4
#define KK 200
#define DIMN 256
#define TFRAMES 800
#define TTILE 8

// ---- scratch (no allocations allowed) ----
__device__ float g_start[BB * KK];
__device__ float g_end[BB * KK];
__device__ float g_base1[BB * KK * 16];
__device__ float g_base2[BB * KK * 2];

// silu(x) = x * sigmoid(x) = 0.5*x*(1 + tanh(x/2)) : 1 MUFU + 2 FMA
__device__ __forceinline__ float silu_f(float x) {
    float hx = 0.5f * x;
    float t;
    asm("tanh.approx.f32 %0, %1;" : "=f"(t) : "f"(hx));
    return fmaf(hx, t, hx);
}

// ---------------------------------------------------------------------------
// Kernel A: blocks 0..99 = conv1d(k=3)+SiLU for 8 tokens each (both branches),
// folding the t-invariant 8 conv features through rows 2..9 of sw1_w1/sw2_w1
// into per-(b,k) base vectors. Block 100 = warp-scan cumsum of durations.
// ---------------------------------------------------------------------------
__global__ __launch_bounds__(256) void prep_kernel(
    const float* __restrict__ dur, const float* __restrict__ features,
    const float* __restrict__ c1w, const float* __restrict__ c1b,
    const float* __restrict__ c2w, const float* __restrict__ c2b,
    const float* __restrict__ sw1w1, const float* __restrict__ sw1b1,
    const float* __restrict__ sw2w1, const float* __restrict__ sw2b1) {
    int tid = threadIdx.x;
    int lane = tid & 31, w = tid >> 5;

    if (blockIdx.x == 100) {
        if (w < BB) {
            float carry = 0.f;
            for (int c = 0; c < 7; c++) {
                int idx = c * 32 + lane;
                float d = (idx < KK) ? dur[w * KK + idx] : 0.f;
                float v = d;
#pragma unroll
                for (int o = 1; o < 32; o <<= 1) {
                    float u = __shfl_up_sync(0xffffffffu, v, o);
                    if (lane >= o) v += u;
                }
                if (idx < KK) {
                    g_end[w * KK + idx] = carry + v;
                    g_start[w * KK + idx] = carry + v - d;
                }
                carry += __shfl_sync(0xffffffffu, v, 31);
            }
        }
        return;
    }

    int b = blockIdx.x / 25;
    int k0 = (blockIdx.x % 25) * 8;
    __shared__ float featS[10][256];   // rows k0-1 .. k0+8
    __shared__ float convS[8][16];     // [token][8 left | 8 right]

    for (int i = tid; i < 2560; i += 256) {
        int r = i >> 8, d = i & 255;
        int row = k0 - 1 + r;
        featS[r][d] = (row >= 0 && row < KK) ? features[(b * KK + row) * DIMN + d] : 0.f;
    }
    __syncthreads();

    float acc[16];
#pragma unroll
    for (int c = 0; c < 16; c++) acc[c] = 0.f;
    for (int it = 0; it < 24; it++) {
        int i = it * 32 + lane;
        int j = i >> 8, d = i & 255;
        float f = featS[w + j][d];
        int off = (j * 256 + d) * 8;          // weights [3,256,8]: w contiguous
        float4 a0 = *reinterpret_cast<const float4*>(c1w + off);
        float4 a1 = *reinterpret_cast<const float4*>(c1w + off + 4);
        float4 b0 = *reinterpret_cast<const float4*>(c2w + off);
        float4 b1 = *reinterpret_cast<const float4*>(c2w + off + 4);
        acc[0] = fmaf(f, a0.x, acc[0]);  acc[1] = fmaf(f, a0.y, acc[1]);
        acc[2] = fmaf(f, a0.z, acc[2]);  acc[3] = fmaf(f, a0.w, acc[3]);
        acc[4] = fmaf(f, a1.x, acc[4]);  acc[5] = fmaf(f, a1.y, acc[5]);
        acc[6] = fmaf(f, a1.z, acc[6]);  acc[7] = fmaf(f, a1.w, acc[7]);
        acc[8]  = fmaf(f, b0.x, acc[8]);  acc[9]  = fmaf(f, b0.y, acc[9]);
        acc[10] = fmaf(f, b0.z, acc[10]); acc[11] = fmaf(f, b0.w, acc[11]);
        acc[12] = fmaf(f, b1.x, acc[12]); acc[13] = fmaf(f, b1.y, acc[13]);
        acc[14] = fmaf(f, b1.z, acc[14]); acc[15] = fmaf(f, b1.w, acc[15]);
    }
#pragma unroll
    for (int c = 0; c < 16; c++) {
        float v = acc[c];
#pragma unroll
        for (int o = 16; o; o >>= 1) v += __shfl_down_sync(0xffffffffu, v, o);
        if (lane == 0) convS[w][c] = v;
    }
    __syncthreads();

    if (tid < 128) {
        int tk = tid >> 4, c = tid & 15;
        float bsl = (c < 8) ? c1b[c] : c2b[c - 8];
        convS[tk][c] = silu_f(convS[tk][c] + bsl);
    }
    __syncthreads();

    if (tid < 128) {
        int tk = tid >> 4, i = tid & 15;
        float s = sw1b1[i];
#pragma unroll
        for (int c = 0; c < 8; c++) s = fmaf(convS[tk][c], sw1w1[(2 + c) * 16 + i], s);
        g_base1[(b * KK + k0 + tk) * 16 + i] = s;
    } else if (tid < 144) {
        int t2 = tid - 128, tk = t2 >> 1, j = t2 & 1;
        float s = sw2b1[j];
#pragma unroll
        for (int c = 0; c < 8; c++) s = fmaf(convS[tk][8 + c], sw2w1[(2 + c) * 2 + j], s);
        g_base2[(b * KK + k0 + tk) * 2 + j] = s;
    }
}

// ---------------------------------------------------------------------------
// Kernel B: fused main. One block = (b, 8 frames).
//   logits (k-parallel) -> 8 warp-parallel softmax
//   C phase: 2 frames register-blocked; loop over i loads W2 row (4 LDS.128)
//   and w1 pair (LDS.64) ONCE, FMAs into both frames' accumulators.
//   W-scaled C rows stored with conflict-free STS.128 (pad 20), tree-reduced.
//   Then one batched O pass reusing each feature load across all 8 frames.
// ---------------------------------------------------------------------------
__global__ __launch_bounds__(256, 3) void main_kernel(
    const float* __restrict__ features,
    const float* __restrict__ sw1w1, const float* __restrict__ sw1w2,
    const float* __restrict__ sw1b2,
    const float* __restrict__ sw2w1, const float* __restrict__ sw2w2,
    const float* __restrict__ sw2b2,
    const float* __restrict__ p1w, const float* __restrict__ p1b,
    const float* __restrict__ p2w, const float* __restrict__ p2b,
    float* __restrict__ out) {
    __shared__ __align__(16) float sE[TTILE][KK];    // logits -> normalized W
    __shared__ __align__(16) float Csm[2][KK][20];   // W-scaled C, pad 20
    __shared__ __align__(16) float sW2s[256];        // sw1_w2 [16,16] row-major
    __shared__ __align__(8)  float sW1p[32];         // interleaved (w1r0[i], w1r1[i])
    __shared__ float sB2[16];
    __shared__ float sPart[2][16][8];
    __shared__ float sA[TTILE][16];

    int tid = threadIdx.x;
    int b = blockIdx.y;
    int t0 = blockIdx.x * TTILE;
    int lane = tid & 31, wid = tid >> 5;

    sW2s[tid] = sw1w2[tid];
    if (tid < 16) {
        sW1p[tid * 2]     = sw1w1[tid];        // row 0 (S weight)
        sW1p[tid * 2 + 1] = sw1w1[16 + tid];   // row 1 (E weight)
        sB2[tid] = sw1b2[tid];
    }

    // tiny uniform constants
    float s2r00 = sw2w1[0], s2r01 = sw2w1[1];
    float s2r10 = sw2w1[2], s2r11 = sw2w1[3];
    float w20 = sw2w2[0], w21 = sw2w2[1], w22 = sw2w2[2], w23 = sw2w2[3];
    float b20 = sw2b2[0], b21 = sw2b2[1];
    float p10 = p1w[0], p11 = p1w[1], pb1 = p1b[0];

    // per-k state in registers (tid < 200)
    float base1[16];
    float base2_0 = 0.f, base2_1 = 0.f, startk = 0.f, endk = 0.f;
    if (tid < KK) {
        startk = g_start[b * KK + tid];
        endk   = g_end[b * KK + tid];
        const float4* bp = reinterpret_cast<const float4*>(g_base1 + (b * KK + tid) * 16);
#pragma unroll
        for (int q = 0; q < 4; q++) {
            float4 v = bp[q];
            base1[q * 4 + 0] = v.x; base1[q * 4 + 1] = v.y;
            base1[q * 4 + 2] = v.z; base1[q * 4 + 3] = v.w;
        }
        base2_0 = g_base2[(b * KK + tid) * 2 + 0];
        base2_1 = g_base2[(b * KK + tid) * 2 + 1];
    }

    // ---- logits for all 8 frames ----
    if (tid < KK) {
#pragma unroll
        for (int tt = 0; tt < TTILE; tt++) {
            float t = (float)(t0 + tt);
            float S = t - startk, E = endk - t;
            float g0  = silu_f(fmaf(S, s2r00, fmaf(E, s2r10, base2_0)));
            float g1  = silu_f(fmaf(S, s2r01, fmaf(E, s2r11, base2_1)));
            float rr0 = silu_f(fmaf(g0, w20, fmaf(g1, w22, b20)));
            float rr1 = silu_f(fmaf(g0, w21, fmaf(g1, w23, b21)));
            sE[tt][tid] = fmaf(rr0, p10, fmaf(rr1, p11, pb1));
        }
    }
    __syncthreads();

    // ---- warp wid: softmax of frame wid, normalized in place ----
    {
        float v[7];
        float m = -1e30f;
#pragma unroll
        for (int c = 0; c < 7; c++) {
            int idx = c * 32 + lane;
            v[c] = (idx < KK) ? sE[wid][idx] : -1e30f;
            m = fmaxf(m, v[c]);
        }
#pragma unroll
        for (int o = 16; o; o >>= 1) m = fmaxf(m, __shfl_xor_sync(0xffffffffu, m, o));
        float s = 0.f;
#pragma unroll
        for (int c = 0; c < 7; c++) {
            v[c] = __expf(v[c] - m);
            if (c * 32 + lane < KK) s += v[c];
        }
#pragma unroll
        for (int o = 16; o; o >>= 1) s += __shfl_xor_sync(0xffffffffu, s, o);
        float invs = 1.0f / s;
#pragma unroll
        for (int c = 0; c < 7; c++) {
            int idx = c * 32 + lane;
            if (idx < KK) sE[wid][idx] = v[c] * invs;
        }
    }
    __syncthreads();

    // ---- C phase + A reduction, 2 register-blocked frames per chunk ----
    const float4* w2v = reinterpret_cast<const float4*>(sW2s);
    const float2* w1v = reinterpret_cast<const float2*>(sW1p);
    for (int half = 0; half < 4; half++) {
        if (tid < KK) {
            float tA = (float)(t0 + half * 2);
            float S0 = tA - startk,        E0 = endk - tA;
            float S1 = S0 + 1.0f,          E1 = E0 - 1.0f;
            float accC[2][16];
#pragma unroll
            for (int j = 0; j < 16; j++) { accC[0][j] = sB2[j]; accC[1][j] = accC[0][j]; }
#pragma unroll
            for (int i = 0; i < 16; i++) {
                float2 wp = w1v[i];                       // (w1r0[i], w1r1[i]) broadcast
                float h0 = silu_f(fmaf(S0, wp.x, fmaf(E0, wp.y, base1[i])));
                float h1 = silu_f(fmaf(S1, wp.x, fmaf(E1, wp.y, base1[i])));
#pragma unroll
                for (int jq = 0; jq < 4; jq++) {
                    float4 wv = w2v[i * 4 + jq];          // W2 row i, broadcast, shared by both frames
                    accC[0][jq * 4 + 0] = fmaf(h0, wv.x, accC[0][jq * 4 + 0]);
                    accC[0][jq * 4 + 1] = fmaf(h0, wv.y, accC[0][jq * 4 + 1]);
                    accC[0][jq * 4 + 2] = fmaf(h0, wv.z, accC[0][jq * 4 + 2]);
                    accC[0][jq * 4 + 3] = fmaf(h0, wv.w, accC[0][jq * 4 + 3]);
                    accC[1][jq * 4 + 0] = fmaf(h1, wv.x, accC[1][jq * 4 + 0]);
                    accC[1][jq * 4 + 1] = fmaf(h1, wv.y, accC[1][jq * 4 + 1]);
                    accC[1][jq * 4 + 2] = fmaf(h1, wv.z, accC[1][jq * 4 + 2]);
                    accC[1][jq * 4 + 3] = fmaf(h1, wv.w, accC[1][jq * 4 + 3]);
                }
            }
            float wk0 = sE[half * 2 + 0][tid];
            float wk1 = sE[half * 2 + 1][tid];
#pragma unroll
            for (int jq = 0; jq < 4; jq++) {
                float4 c0, c1;
                c0.x = wk0 * silu_f(accC[0][jq * 4 + 0]);
                c0.y = wk0 * silu_f(accC[0][jq * 4 + 1]);
                c0.z = wk0 * silu_f(accC[0][jq * 4 + 2]);
                c0.w = wk0 * silu_f(accC[0][jq * 4 + 3]);
                c1.x = wk1 * silu_f(accC[1][jq * 4 + 0]);
                c1.y = wk1 * silu_f(accC[1][jq * 4 + 1]);
                c1.z = wk1 * silu_f(accC[1][jq * 4 + 2]);
                c1.w = wk1 * silu_f(accC[1][jq * 4 + 3]);
                *reinterpret_cast<float4*>(&Csm[0][tid][jq * 4]) = c0;
                *reinterpret_cast<float4*>(&Csm[1][tid][jq * 4]) = c1;
            }
        }
        __syncthreads();
        {   // stage 1: (u, p, ch-of-25)
            int u = tid >> 7, p = (tid >> 3) & 15, ch = tid & 7;
            float s = 0.f;
            int kbeg = ch * 25;
            for (int k = kbeg; k < kbeg + 25; k++) s += Csm[u][k][p];
            sPart[u][p][ch] = s;
        }
        __syncthreads();
        if (tid < 32) {  // stage 2
            int u = tid >> 4, p = tid & 15;
            float s = 0.f;
#pragma unroll
            for (int ch = 0; ch < 8; ch++) s += sPart[u][p][ch];
            sA[half * 2 + u][p] = s;
        }
        __syncthreads();
    }

    // ---- O phase: acc[tt][d] = sum_k W[tt][k]*F[k][d], feature loads reused 8x
    float acc[TTILE];
#pragma unroll
    for (int tt = 0; tt < TTILE; tt++) acc[tt] = 0.f;

    const float* F = features + b * KK * DIMN + tid;
    for (int k = 0; k < KK; k += 4) {
        float f0 = F[(k + 0) * DIMN];
        float f1 = F[(k + 1) * DIMN];
        float f2 = F[(k + 2) * DIMN];
        float f3 = F[(k + 3) * DIMN];
#pragma unroll
        for (int tt = 0; tt < TTILE; tt++) {
            float4 w4 = *reinterpret_cast<const float4*>(&sE[tt][k]);
            acc[tt] = fmaf(w4.x, f0, acc[tt]);
            acc[tt] = fmaf(w4.y, f1, acc[tt]);
            acc[tt] = fmaf(w4.z, f2, acc[tt]);
            acc[tt] = fmaf(w4.w, f3, acc[tt]);
        }
    }

    float p2wr[16];
#pragma unroll
    for (int q = 0; q < 16; q++) p2wr[q] = p2w[q * DIMN + tid];
    float pb = p2b[tid];
#pragma unroll
    for (int tt = 0; tt < TTILE; tt++) {
        float r = acc[tt] + pb;
#pragma unroll
        for (int q = 0; q < 16; q++) r = fmaf(sA[tt][q], p2wr[q], r);
        out[((b * TFRAMES) + t0 + tt) * DIMN + tid] = r;
    }
}

// ---------------------------------------------------------------------------
extern "C" void kernel_launch(void* const* d_in, const int* in_sizes, int n_in,
                              void* d_out, int out_size) {
    const float* dur      = (const float*)d_in[1];
    const float* features = (const float*)d_in[2];
    const float* c1w      = (const float*)d_in[3];
    const float* c1b      = (const float*)d_in[4];
    const float* c2w      = (const float*)d_in[5];
    const float* c2b      = (const float*)d_in[6];
    const float* sw1w1    = (const float*)d_in[7];
    const float* sw1b1    = (const float*)d_in[8];
    const float* sw1w2    = (const float*)d_in[9];
    const float* sw1b2    = (const float*)d_in[10];
    const float* sw2w1    = (const float*)d_in[11];
    const float* sw2b1    = (const float*)d_in[12];
    const float* sw2w2    = (const float*)d_in[13];
    const float* sw2b2    = (const float*)d_in[14];
    const float* p1w      = (const float*)d_in[15];
    const float* p1b      = (const float*)d_in[16];
    const float* p2w      = (const float*)d_in[17];
    const float* p2b      = (const float*)d_in[18];
    float* out = (float*)d_out;

    prep_kernel<<<101, 256>>>(dur, features, c1w, c1b, c2w, c2b,
                              sw1w1, sw1b1, sw2w1, sw2b1);
    main_kernel<<<dim3(TFRAMES / TTILE, BB), 256>>>(
        features, sw1w1, sw1w2, sw1b2, sw2w1, sw2w2, sw2b2,
        p1w, p1b, p2w, p2b, out);
}

// round 10
// speedup vs baseline: 3.1145x; 1.0703x over previous
#include <cuda_runtime.h>

#define BB 4
#define KK 200
#define DIMN 256
#define TFRAMES 800
#define TTILE 8

// ---- scratch (no allocations allowed) ----
__device__ float g_start[BB * KK];
__device__ float g_end[BB * KK];
__device__ float g_base1[BB * KK * 16];
__device__ float g_base2[BB * KK * 2];

// silu(x) = x * sigmoid(x) = 0.5*x*(1 + tanh(x/2)) : 1 MUFU + 2 FMA
__device__ __forceinline__ float silu_f(float x) {
    float hx = 0.5f * x;
    float t;
    asm("tanh.approx.f32 %0, %1;" : "=f"(t) : "f"(hx));
    return fmaf(hx, t, hx);
}

// ---- packed f32x2 helpers (sm_100+; FFMA2 is PTX-only, ptxas won't fuse) ----
typedef unsigned long long u64t;
__device__ __forceinline__ u64t pack2(float lo, float hi) {
    u64t r;
    asm("mov.b64 %0, {%1, %2};" : "=l"(r) : "f"(lo), "f"(hi));
    return r;
}
__device__ __forceinline__ void unpack2(u64t v, float& lo, float& hi) {
    asm("mov.b64 {%0, %1}, %2;" : "=f"(lo), "=f"(hi) : "l"(v));
}
__device__ __forceinline__ u64t fma2(u64t a, u64t b, u64t c) {
    u64t d;
    asm("fma.rn.f32x2 %0, %1, %2, %3;" : "=l"(d) : "l"(a), "l"(b), "l"(c));
    return d;
}

// ---------------------------------------------------------------------------
// Kernel A: blocks 0..99 = conv1d(k=3)+SiLU for 8 tokens each (both branches),
// folding the t-invariant 8 conv features through rows 2..9 of sw1_w1/sw2_w1
// into per-(b,k) base vectors. Block 100 = warp-scan cumsum of durations.
// ---------------------------------------------------------------------------
__global__ __launch_bounds__(256) void prep_kernel(
    const float* __restrict__ dur, const float* __restrict__ features,
    const float* __restrict__ c1w, const float* __restrict__ c1b,
    const float* __restrict__ c2w, const float* __restrict__ c2b,
    const float* __restrict__ sw1w1, const float* __restrict__ sw1b1,
    const float* __restrict__ sw2w1, const float* __restrict__ sw2b1) {
    int tid = threadIdx.x;
    int lane = tid & 31, w = tid >> 5;

    if (blockIdx.x == 100) {
        if (w < BB) {
            float carry = 0.f;
            for (int c = 0; c < 7; c++) {
                int idx = c * 32 + lane;
                float d = (idx < KK) ? dur[w * KK + idx] : 0.f;
                float v = d;
#pragma unroll
                for (int o = 1; o < 32; o <<= 1) {
                    float u = __shfl_up_sync(0xffffffffu, v, o);
                    if (lane >= o) v += u;
                }
                if (idx < KK) {
                    g_end[w * KK + idx] = carry + v;
                    g_start[w * KK + idx] = carry + v - d;
                }
                carry += __shfl_sync(0xffffffffu, v, 31);
            }
        }
        return;
    }

    int b = blockIdx.x / 25;
    int k0 = (blockIdx.x % 25) * 8;
    __shared__ float featS[10][256];   // rows k0-1 .. k0+8
    __shared__ float convS[8][16];     // [token][8 left | 8 right]

    for (int i = tid; i < 2560; i += 256) {
        int r = i >> 8, d = i & 255;
        int row = k0 - 1 + r;
        featS[r][d] = (row >= 0 && row < KK) ? features[(b * KK + row) * DIMN + d] : 0.f;
    }
    __syncthreads();

    float acc[16];
#pragma unroll
    for (int c = 0; c < 16; c++) acc[c] = 0.f;
    for (int it = 0; it < 24; it++) {
        int i = it * 32 + lane;
        int j = i >> 8, d = i & 255;
        float f = featS[w + j][d];
        int off = (j * 256 + d) * 8;          // weights [3,256,8]: w contiguous
        float4 a0 = *reinterpret_cast<const float4*>(c1w + off);
        float4 a1 = *reinterpret_cast<const float4*>(c1w + off + 4);
        float4 b0 = *reinterpret_cast<const float4*>(c2w + off);
        float4 b1 = *reinterpret_cast<const float4*>(c2w + off + 4);
        acc[0] = fmaf(f, a0.x, acc[0]);  acc[1] = fmaf(f, a0.y, acc[1]);
        acc[2] = fmaf(f, a0.z, acc[2]);  acc[3] = fmaf(f, a0.w, acc[3]);
        acc[4] = fmaf(f, a1.x, acc[4]);  acc[5] = fmaf(f, a1.y, acc[5]);
        acc[6] = fmaf(f, a1.z, acc[6]);  acc[7] = fmaf(f, a1.w, acc[7]);
        acc[8]  = fmaf(f, b0.x, acc[8]);  acc[9]  = fmaf(f, b0.y, acc[9]);
        acc[10] = fmaf(f, b0.z, acc[10]); acc[11] = fmaf(f, b0.w, acc[11]);
        acc[12] = fmaf(f, b1.x, acc[12]); acc[13] = fmaf(f, b1.y, acc[13]);
        acc[14] = fmaf(f, b1.z, acc[14]); acc[15] = fmaf(f, b1.w, acc[15]);
    }
#pragma unroll
    for (int c = 0; c < 16; c++) {
        float v = acc[c];
#pragma unroll
        for (int o = 16; o; o >>= 1) v += __shfl_down_sync(0xffffffffu, v, o);
        if (lane == 0) convS[w][c] = v;
    }
    __syncthreads();

    if (tid < 128) {
        int tk = tid >> 4, c = tid & 15;
        float bsl = (c < 8) ? c1b[c] : c2b[c - 8];
        convS[tk][c] = silu_f(convS[tk][c] + bsl);
    }
    __syncthreads();

    if (tid < 128) {
        int tk = tid >> 4, i = tid & 15;
        float s = sw1b1[i];
#pragma unroll
        for (int c = 0; c < 8; c++) s = fmaf(convS[tk][c], sw1w1[(2 + c) * 16 + i], s);
        g_base1[(b * KK + k0 + tk) * 16 + i] = s;
    } else if (tid < 144) {
        int t2 = tid - 128, tk = t2 >> 1, j = t2 & 1;
        float s = sw2b1[j];
#pragma unroll
        for (int c = 0; c < 8; c++) s = fmaf(convS[tk][8 + c], sw2w1[(2 + c) * 2 + j], s);
        g_base2[(b * KK + k0 + tk) * 2 + j] = s;
    }
}

// ---------------------------------------------------------------------------
// Kernel B: fused main. One block = (b, 8 frames).
//   logits (k-parallel) -> 8 warp-parallel softmax
//   C phase: 2 frames register-blocked, j-dimension packed in f32x2 (FFMA2),
//   W2 row loaded once per i (4 LDS.128 shared by both frames).
//   O phase: k-dimension packed in f32x2; weight pairs free from LDS.128.
// ---------------------------------------------------------------------------
__global__ __launch_bounds__(256, 3) void main_kernel(
    const float* __restrict__ features,
    const float* __restrict__ sw1w1, const float* __restrict__ sw1w2,
    const float* __restrict__ sw1b2,
    const float* __restrict__ sw2w1, const float* __restrict__ sw2w2,
    const float* __restrict__ sw2b2,
    const float* __restrict__ p1w, const float* __restrict__ p1b,
    const float* __restrict__ p2w, const float* __restrict__ p2b,
    float* __restrict__ out) {
    __shared__ __align__(16) float sE[TTILE][KK];    // logits -> normalized W
    __shared__ __align__(16) float Csm[2][KK][20];   // W-scaled C, pad 20
    __shared__ __align__(16) float sW2s[256];        // sw1_w2 [16,16] row-major
    __shared__ __align__(16) float sW1p[32];         // interleaved (w1r0[i], w1r1[i])
    __shared__ __align__(16) float sB2[16];
    __shared__ float sPart[2][16][8];
    __shared__ float sA[TTILE][16];

    int tid = threadIdx.x;
    int b = blockIdx.y;
    int t0 = blockIdx.x * TTILE;
    int lane = tid & 31, wid = tid >> 5;

    sW2s[tid] = sw1w2[tid];
    if (tid < 16) {
        sW1p[tid * 2]     = sw1w1[tid];        // row 0 (S weight)
        sW1p[tid * 2 + 1] = sw1w1[16 + tid];   // row 1 (E weight)
        sB2[tid] = sw1b2[tid];
    }

    // tiny uniform constants
    float s2r00 = sw2w1[0], s2r01 = sw2w1[1];
    float s2r10 = sw2w1[2], s2r11 = sw2w1[3];
    float w20 = sw2w2[0], w21 = sw2w2[1], w22 = sw2w2[2], w23 = sw2w2[3];
    float b20 = sw2b2[0], b21 = sw2b2[1];
    float p10 = p1w[0], p11 = p1w[1], pb1 = p1b[0];

    // per-k state in registers (tid < 200)
    float base1[16];
    float base2_0 = 0.f, base2_1 = 0.f, startk = 0.f, endk = 0.f;
    if (tid < KK) {
        startk = g_start[b * KK + tid];
        endk   = g_end[b * KK + tid];
        const float4* bp = reinterpret_cast<const float4*>(g_base1 + (b * KK + tid) * 16);
#pragma unroll
        for (int q = 0; q < 4; q++) {
            float4 v = bp[q];
            base1[q * 4 + 0] = v.x; base1[q * 4 + 1] = v.y;
            base1[q * 4 + 2] = v.z; base1[q * 4 + 3] = v.w;
        }
        base2_0 = g_base2[(b * KK + tid) * 2 + 0];
        base2_1 = g_base2[(b * KK + tid) * 2 + 1];
    }

    // ---- logits for all 8 frames ----
    if (tid < KK) {
#pragma unroll
        for (int tt = 0; tt < TTILE; tt++) {
            float t = (float)(t0 + tt);
            float S = t - startk, E = endk - t;
            float g0  = silu_f(fmaf(S, s2r00, fmaf(E, s2r10, base2_0)));
            float g1  = silu_f(fmaf(S, s2r01, fmaf(E, s2r11, base2_1)));
            float rr0 = silu_f(fmaf(g0, w20, fmaf(g1, w22, b20)));
            float rr1 = silu_f(fmaf(g0, w21, fmaf(g1, w23, b21)));
            sE[tt][tid] = fmaf(rr0, p10, fmaf(rr1, p11, pb1));
        }
    }
    __syncthreads();

    // ---- warp wid: softmax of frame wid, normalized in place ----
    {
        float v[7];
        float m = -1e30f;
#pragma unroll
        for (int c = 0; c < 7; c++) {
            int idx = c * 32 + lane;
            v[c] = (idx < KK) ? sE[wid][idx] : -1e30f;
            m = fmaxf(m, v[c]);
        }
#pragma unroll
        for (int o = 16; o; o >>= 1) m = fmaxf(m, __shfl_xor_sync(0xffffffffu, m, o));
        float s = 0.f;
#pragma unroll
        for (int c = 0; c < 7; c++) {
            v[c] = __expf(v[c] - m);
            if (c * 32 + lane < KK) s += v[c];
        }
#pragma unroll
        for (int o = 16; o; o >>= 1) s += __shfl_xor_sync(0xffffffffu, s, o);
        float invs = 1.0f / s;
#pragma unroll
        for (int c = 0; c < 7; c++) {
            int idx = c * 32 + lane;
            if (idx < KK) sE[wid][idx] = v[c] * invs;
        }
    }
    __syncthreads();

    // ---- C phase + A reduction, 2 register-blocked frames, FFMA2 on j ----
    const float2* w1v = reinterpret_cast<const float2*>(sW1p);
    for (int half = 0; half < 4; half++) {
        if (tid < KK) {
            float tA = (float)(t0 + half * 2);
            float S0 = tA - startk,        E0 = endk - tA;
            float S1 = S0 + 1.0f,          E1 = E0 - 1.0f;
            u64t accC2[2][8];
            {
                const u64t* b2v = reinterpret_cast<const u64t*>(sB2);
#pragma unroll
                for (int j2 = 0; j2 < 8; j2++) {
                    u64t bv = b2v[j2];
                    accC2[0][j2] = bv;
                    accC2[1][j2] = bv;
                }
            }
#pragma unroll
            for (int i = 0; i < 16; i++) {
                float2 wp = w1v[i];                       // (w1r0[i], w1r1[i]) broadcast
                float h0 = silu_f(fmaf(S0, wp.x, fmaf(E0, wp.y, base1[i])));
                float h1 = silu_f(fmaf(S1, wp.x, fmaf(E1, wp.y, base1[i])));
                u64t h02 = pack2(h0, h0);
                u64t h12 = pack2(h1, h1);
                const ulonglong2* wrow = reinterpret_cast<const ulonglong2*>(sW2s + i * 16);
#pragma unroll
                for (int jq = 0; jq < 4; jq++) {
                    ulonglong2 wv = wrow[jq];             // 1 LDS.128 -> 2 f32x2
                    accC2[0][jq * 2 + 0] = fma2(h02, wv.x, accC2[0][jq * 2 + 0]);
                    accC2[0][jq * 2 + 1] = fma2(h02, wv.y, accC2[0][jq * 2 + 1]);
                    accC2[1][jq * 2 + 0] = fma2(h12, wv.x, accC2[1][jq * 2 + 0]);
                    accC2[1][jq * 2 + 1] = fma2(h12, wv.y, accC2[1][jq * 2 + 1]);
                }
            }
            float wk0 = sE[half * 2 + 0][tid];
            float wk1 = sE[half * 2 + 1][tid];
#pragma unroll
            for (int jq = 0; jq < 4; jq++) {
                float a0, a1, a2, a3;
                float4 c0, c1;
                unpack2(accC2[0][jq * 2 + 0], a0, a1);
                unpack2(accC2[0][jq * 2 + 1], a2, a3);
                c0.x = wk0 * silu_f(a0); c0.y = wk0 * silu_f(a1);
                c0.z = wk0 * silu_f(a2); c0.w = wk0 * silu_f(a3);
                unpack2(accC2[1][jq * 2 + 0], a0, a1);
                unpack2(accC2[1][jq * 2 + 1], a2, a3);
                c1.x = wk1 * silu_f(a0); c1.y = wk1 * silu_f(a1);
                c1.z = wk1 * silu_f(a2); c1.w = wk1 * silu_f(a3);
                *reinterpret_cast<float4*>(&Csm[0][tid][jq * 4]) = c0;
                *reinterpret_cast<float4*>(&Csm[1][tid][jq * 4]) = c1;
            }
        }
        __syncthreads();
        {   // stage 1: (u, p, ch-of-25)
            int u = tid >> 7, p = (tid >> 3) & 15, ch = tid & 7;
            float s = 0.f;
            int kbeg = ch * 25;
            for (int k = kbeg; k < kbeg + 25; k++) s += Csm[u][k][p];
            sPart[u][p][ch] = s;
        }
        __syncthreads();
        if (tid < 32) {  // stage 2
            int u = tid >> 4, p = tid & 15;
            float s = 0.f;
#pragma unroll
            for (int ch = 0; ch < 8; ch++) s += sPart[u][p][ch];
            sA[half * 2 + u][p] = s;
        }
        __syncthreads();
    }

    // ---- O phase: FFMA2 on k (even/odd partial sums per frame) ----
    u64t acc2[TTILE];
#pragma unroll
    for (int tt = 0; tt < TTILE; tt++) acc2[tt] = 0ull;

    const float* F = features + b * KK * DIMN + tid;
    for (int k = 0; k < KK; k += 4) {
        float f0 = F[(k + 0) * DIMN];
        float f1 = F[(k + 1) * DIMN];
        float f2 = F[(k + 2) * DIMN];
        float f3 = F[(k + 3) * DIMN];
        u64t f01 = pack2(f0, f1);
        u64t f23 = pack2(f2, f3);
#pragma unroll
        for (int tt = 0; tt < TTILE; tt++) {
            ulonglong2 w2 = *reinterpret_cast<const ulonglong2*>(&sE[tt][k]); // (w_k,w_k+1),(w_k+2,w_k+3)
            acc2[tt] = fma2(f01, w2.x, acc2[tt]);
            acc2[tt] = fma2(f23, w2.y, acc2[tt]);
        }
    }

    float p2wr[16];
#pragma unroll
    for (int q = 0; q < 16; q++) p2wr[q] = p2w[q * DIMN + tid];
    float pb = p2b[tid];
#pragma unroll
    for (int tt = 0; tt < TTILE; tt++) {
        float lo, hi;
        unpack2(acc2[tt], lo, hi);
        float r = lo + hi + pb;
#pragma unroll
        for (int q = 0; q < 16; q++) r = fmaf(sA[tt][q], p2wr[q], r);
        out[((b * TFRAMES) + t0 + tt) * DIMN + tid] = r;
    }
}

// ---------------------------------------------------------------------------
extern "C" void kernel_launch(void* const* d_in, const int* in_sizes, int n_in,
                              void* d_out, int out_size) {
    const float* dur      = (const float*)d_in[1];
    const float* features = (const float*)d_in[2];
    const float* c1w      = (const float*)d_in[3];
    const float* c1b      = (const float*)d_in[4];
    const float* c2w      = (const float*)d_in[5];
    const float* c2b      = (const float*)d_in[6];
    const float* sw1w1    = (const float*)d_in[7];
    const float* sw1b1    = (const float*)d_in[8];
    const float* sw1w2    = (const float*)d_in[9];
    const float* sw1b2    = (const float*)d_in[10];
    const float* sw2w1    = (const float*)d_in[11];
    const float* sw2b1    = (const float*)d_in[12];
    const float* sw2w2    = (const float*)d_in[13];
    const float* sw2b2    = (const float*)d_in[14];
    const float* p1w      = (const float*)d_in[15];
    const float* p1b      = (const float*)d_in[16];
    const float* p2w      = (const float*)d_in[17];
    const float* p2b      = (const float*)d_in[18];
    float* out = (float*)d_out;

    prep_kernel<<<101, 256>>>(dur, features, c1w, c1b, c2w, c2b,
                              sw1w1, sw1b1, sw2w1, sw2b1);
    main_kernel<<<dim3(TFRAMES / TTILE, BB), 256>>>(
        features, sw1w1, sw1w2, sw1b2, sw2w1, sw2w2, sw2b2,
        p1w, p1b, p2w, p2b, out);
}